// round 2
// baseline (speedup 1.0000x reference)
#include <cuda_runtime.h>
#include <math.h>

// Problem dims
#define BDIM 2048
#define ODIM 256
#define IDIM 256

// Scratch (no cudaMalloc allowed): transposed [j][b] / [j][i] layouts so the
// main kernel's gmem loads are coalesced along b / i.
__device__ float g_u[IDIM * BDIM];  // K * cos(phi0 + x[b,j]), laid out [j][b]
__device__ float g_v[IDIM * BDIM];  // K * sin(phi0 + x[b,j]), laid out [j][b]
__device__ float g_p[IDIM * ODIM];  // cos(off[i,j]), laid out [j][i]
__device__ float g_q[IDIM * ODIM];  // sin(off[i,j]), laid out [j][i]

__device__ __forceinline__ float frcp(float x) {
    float r;
    asm("rcp.approx.ftz.f32 %0, %1;" : "=f"(r) : "f"(x));
    return r;
}

__global__ void prep_uv(const float* __restrict__ x, float K, float phi0) {
    int idx = blockIdx.x * blockDim.x + threadIdx.x;  // < BDIM*IDIM
    int b = idx >> 8;        // IDIM = 256
    int j = idx & 255;
    float s, c;
    sincosf(phi0 + x[idx], &s, &c);
    g_u[j * BDIM + b] = K * c;
    g_v[j * BDIM + b] = K * s;
}

__global__ void prep_pq(const float* __restrict__ off) {
    int idx = blockIdx.x * blockDim.x + threadIdx.x;  // < ODIM*IDIM
    int i = idx >> 8;
    int j = idx & 255;
    float s, c;
    sincosf(off[idx], &s, &c);
    g_p[j * ODIM + i] = c;
    g_q[j * ODIM + i] = s;
}

// GEMM-style tiling: BM=64 (batch), BN=32 (outputs), BK=32 (inputs),
// 256 threads, each computes a 4(b) x 2(i) micro-tile.
// out[b,i] = IDIM + D * sum_j 1/(C2 - u'[b,j]*p[i,j] + v'[b,j]*q[i,j])
__global__ __launch_bounds__(256, 2) void photonic_main(float* __restrict__ out,
                                                        float C2, float D) {
    __shared__ float su[2][32][64];
    __shared__ float sv[2][32][64];
    __shared__ float sp[2][32][32];
    __shared__ float sq[2][32][32];

    const int tid = threadIdx.x;
    const int i0 = blockIdx.x * 32;   // output-column tile
    const int b0 = blockIdx.y * 64;   // batch-row tile

    // compute-side indices
    const int bl = (tid & 15) * 4;    // 4 consecutive b per thread
    const int il = (tid >> 4) * 2;    // 2 consecutive i per thread

    // loader-side indices (u/v: 2048 floats/chunk -> 2 float4 per thread)
    const int urow = tid >> 4;        // 16 float4 per 64-float row
    const int ucol = (tid & 15) * 4;
    // (p/q: 1024 floats/chunk -> 1 float4 per thread)
    const int prow = tid >> 3;        // 8 float4 per 32-float row
    const int pcol = (tid & 7) * 4;

    float4 ru0, ru1, rv0, rv1, rp, rq;

    auto load_chunk = [&](int j0) {
        ru0 = *(const float4*)(g_u + (j0 + urow) * BDIM + b0 + ucol);
        ru1 = *(const float4*)(g_u + (j0 + urow + 16) * BDIM + b0 + ucol);
        rv0 = *(const float4*)(g_v + (j0 + urow) * BDIM + b0 + ucol);
        rv1 = *(const float4*)(g_v + (j0 + urow + 16) * BDIM + b0 + ucol);
        rp  = *(const float4*)(g_p + (j0 + prow) * ODIM + i0 + pcol);
        rq  = *(const float4*)(g_q + (j0 + prow) * ODIM + i0 + pcol);
    };
    auto store_chunk = [&](int buf) {
        *(float4*)&su[buf][urow][ucol]      = ru0;
        *(float4*)&su[buf][urow + 16][ucol] = ru1;
        *(float4*)&sv[buf][urow][ucol]      = rv0;
        *(float4*)&sv[buf][urow + 16][ucol] = rv1;
        *(float4*)&sp[buf][prow][pcol]      = rp;
        *(float4*)&sq[buf][prow][pcol]      = rq;
    };

    float acc[4][2];
#pragma unroll
    for (int bb = 0; bb < 4; bb++) {
        acc[bb][0] = 0.0f;
        acc[bb][1] = 0.0f;
    }

    load_chunk(0);
    store_chunk(0);
    __syncthreads();

    const int NCHUNK = IDIM / 32;  // 8
    for (int c = 0; c < NCHUNK; c++) {
        const int buf = c & 1;
        if (c + 1 < NCHUNK) load_chunk((c + 1) * 32);

#pragma unroll 8
        for (int jj = 0; jj < 32; jj++) {
            float4 U = *(const float4*)&su[buf][jj][bl];
            float4 V = *(const float4*)&sv[buf][jj][bl];
            float2 P = *(const float2*)&sp[buf][jj][il];
            float2 Q = *(const float2*)&sq[buf][jj][il];
            float u[4] = {U.x, U.y, U.z, U.w};
            float v[4] = {V.x, V.y, V.z, V.w};
#pragma unroll
            for (int bb = 0; bb < 4; bb++) {
                float d0 = fmaf(v[bb], Q.x, C2);
                d0 = fmaf(-u[bb], P.x, d0);
                float d1 = fmaf(v[bb], Q.y, C2);
                d1 = fmaf(-u[bb], P.y, d1);
                acc[bb][0] += frcp(d0);
                acc[bb][1] += frcp(d1);
            }
        }

        if (c + 1 < NCHUNK) store_chunk((c + 1) & 1);
        __syncthreads();
    }

    // Epilogue: out[b, i], shape [BDIM, ODIM]
    float* op = out + (size_t)(b0 + bl) * ODIM + i0 + il;
#pragma unroll
    for (int bb = 0; bb < 4; bb++) {
        float2 r;
        r.x = fmaf(D, acc[bb][0], (float)IDIM);
        r.y = fmaf(D, acc[bb][1], (float)IDIM);
        *(float2*)(op + (size_t)bb * ODIM) = r;
    }
}

extern "C" void kernel_launch(void* const* d_in, const int* in_sizes, int n_in,
                              void* d_out, int out_size) {
    const float* x   = (const float*)d_in[0];  // input_matrix [2048, 256]
    const float* off = (const float*)d_in[1];  // phase_offset [256, 256]
    float* out = (float*)d_out;                // [2048, 256]

    const double PI = 3.14159265358979323846;
    const double RADIUS = 5e-6, KAPPA = 0.1, N_EFF = 3.48, LAMBDA = 1.55e-6,
                 LOSS_A = 0.99;
    double t = sqrt(1.0 - KAPPA);
    double at = LOSS_A * t;
    float K  = (float)(2.0 * at);
    float C2 = (float)(1.0 + at * at);
    float D  = (float)(-(1.0 - t * t) * (1.0 - LOSS_A * LOSS_A));
    float phi0 = (float)fmod(2.0 * PI * N_EFF * (2.0 * PI * RADIUS) / LAMBDA,
                             2.0 * PI);

    prep_uv<<<(BDIM * IDIM) / 256, 256>>>(x, K, phi0);
    prep_pq<<<(ODIM * IDIM) / 256, 256>>>(off);

    dim3 grid(ODIM / 32, BDIM / 64);  // (8, 32) = 256 blocks
    photonic_main<<<grid, 256>>>(out, C2, D);
}

// round 3
// speedup vs baseline: 1.3120x; 1.3120x over previous
#include <cuda_runtime.h>
#include <math.h>

// Problem dims
#define BDIM 2048
#define ODIM 256
#define IDIM 256

typedef unsigned long long u64;

// Scratch (no cudaMalloc allowed).
// g_u[j][b] = -K*cos(phi0 + x[b,j])   (sign folded for fma)
// g_v[j][b] =  K*sin(phi0 + x[b,j])
// g_pd[j][2i..2i+1] = {cos(off[i,j]), cos(off[i,j])}   (duplicated for f32x2 bcast)
// g_qd[j][2i..2i+1] = {sin(off[i,j]), sin(off[i,j])}
__device__ float g_u[IDIM * BDIM];
__device__ float g_v[IDIM * BDIM];
__device__ float g_pd[IDIM * 2 * ODIM];
__device__ float g_qd[IDIM * 2 * ODIM];

// ---------- packed f32x2 helpers (sm_100+) ----------
__device__ __forceinline__ u64 fma2(u64 a, u64 b, u64 c) {
    u64 d;
    asm("fma.rn.f32x2 %0, %1, %2, %3;" : "=l"(d) : "l"(a), "l"(b), "l"(c));
    return d;
}
__device__ __forceinline__ u64 add2(u64 a, u64 b) {
    u64 d;
    asm("add.rn.f32x2 %0, %1, %2;" : "=l"(d) : "l"(a), "l"(b));
    return d;
}
__device__ __forceinline__ u64 mul2(u64 a, u64 b) {
    u64 d;
    asm("mul.rn.f32x2 %0, %1, %2;" : "=l"(d) : "l"(a), "l"(b));
    return d;
}
__device__ __forceinline__ float frcp(float x) {
    float r;
    asm("rcp.approx.ftz.f32 %0, %1;" : "=f"(r) : "f"(x));
    return r;
}
__device__ __forceinline__ u64 rcp2(u64 x) {
    float lo, hi;
    asm("mov.b64 {%0, %1}, %2;" : "=f"(lo), "=f"(hi) : "l"(x));
    lo = frcp(lo);
    hi = frcp(hi);
    u64 r;
    asm("mov.b64 %0, {%1, %2};" : "=l"(r) : "f"(lo), "f"(hi));
    return r;
}
__device__ __forceinline__ u64 pack2(float lo, float hi) {
    u64 r;
    asm("mov.b64 %0, {%1, %2};" : "=l"(r) : "f"(lo), "f"(hi));
    return r;
}
__device__ __forceinline__ void unpack2(u64 v, float& lo, float& hi) {
    asm("mov.b64 {%0, %1}, %2;" : "=f"(lo), "=f"(hi) : "l"(v));
}

// ---------- prep: coalesced both ways via smem tile transpose ----------
// grid (IDIM/32, BDIM/32), 256 threads. Reads x[b][j] coalesced, writes
// g_u/g_v[j][b] coalesced.
__global__ void prep_uv(const float* __restrict__ x, float K, float phi0) {
    __shared__ float tc[32][33];
    __shared__ float ts[32][33];
    const int j0 = blockIdx.x * 32;
    const int b0 = blockIdx.y * 32;
#pragma unroll
    for (int k = 0; k < 4; k++) {
        int lin = threadIdx.x + k * 256;
        int bl = lin >> 5, jl = lin & 31;
        float s, c;
        __sincosf(phi0 + x[(b0 + bl) * IDIM + j0 + jl], &s, &c);
        tc[jl][bl] = c;
        ts[jl][bl] = s;
    }
    __syncthreads();
#pragma unroll
    for (int k = 0; k < 4; k++) {
        int lin = threadIdx.x + k * 256;
        int jl = lin >> 5, bl = lin & 31;
        g_u[(j0 + jl) * BDIM + b0 + bl] = -K * tc[jl][bl];
        g_v[(j0 + jl) * BDIM + b0 + bl] = K * ts[jl][bl];
    }
}

// grid (IDIM/32, ODIM/32), 256 threads. Writes duplicated pairs (float2).
__global__ void prep_pq(const float* __restrict__ off) {
    __shared__ float tc[32][33];
    __shared__ float ts[32][33];
    const int j0 = blockIdx.x * 32;
    const int i0 = blockIdx.y * 32;
#pragma unroll
    for (int k = 0; k < 4; k++) {
        int lin = threadIdx.x + k * 256;
        int il = lin >> 5, jl = lin & 31;
        float s, c;
        __sincosf(off[(i0 + il) * IDIM + j0 + jl], &s, &c);
        tc[jl][il] = c;
        ts[jl][il] = s;
    }
    __syncthreads();
#pragma unroll
    for (int k = 0; k < 4; k++) {
        int lin = threadIdx.x + k * 256;
        int jl = lin >> 5, il = lin & 31;
        float c = tc[jl][il], s = ts[jl][il];
        float2 cc = {c, c}, ss = {s, s};
        *(float2*)&g_pd[(j0 + jl) * (2 * ODIM) + 2 * (i0 + il)] = cc;
        *(float2*)&g_qd[(j0 + jl) * (2 * ODIM) + 2 * (i0 + il)] = ss;
    }
}

// ---------- main: BM=64, BN=32, BK=16, 256 thr, 4b x 2i per thread ----------
// out[b,i] = IDIM + D * sum_j 1/(C2 + g_u[j,b]*p[i,j] + g_v[j,b]*q[i,j])
// Packed over b-pairs (f32x2); j processed in pairs: 1/d0+1/d1 = (d0+d1)*rcp(d0*d1).
__global__ __launch_bounds__(256, 2) void photonic_main(float* __restrict__ out,
                                                        float C2, float D) {
    __shared__ float su[2][16][64];
    __shared__ float sv[2][16][64];
    __shared__ float sp[2][16][64];
    __shared__ float sq[2][16][64];

    const int tid = threadIdx.x;
    const int i0 = blockIdx.x * 32;
    const int b0 = blockIdx.y * 64;

    const int bl = (tid & 15) * 4;   // 4 consecutive b (2 packed pairs)
    const int il = (tid >> 4) * 2;   // 2 consecutive i

    const int lrow = tid >> 4;        // 0..15
    const int lcol = (tid & 15) * 4;  // 0..60

    float4 ru, rv, rp, rq;
    auto load_chunk = [&](int jc) {
        ru = *(const float4*)(g_u + (size_t)(jc + lrow) * BDIM + b0 + lcol);
        rv = *(const float4*)(g_v + (size_t)(jc + lrow) * BDIM + b0 + lcol);
        rp = *(const float4*)(g_pd + (size_t)(jc + lrow) * (2 * ODIM) + 2 * i0 + lcol);
        rq = *(const float4*)(g_qd + (size_t)(jc + lrow) * (2 * ODIM) + 2 * i0 + lcol);
    };
    auto store_chunk = [&](int buf) {
        *(float4*)&su[buf][lrow][lcol] = ru;
        *(float4*)&sv[buf][lrow][lcol] = rv;
        *(float4*)&sp[buf][lrow][lcol] = rp;
        *(float4*)&sq[buf][lrow][lcol] = rq;
    };

    u64 acc00 = 0ull, acc01 = 0ull, acc10 = 0ull, acc11 = 0ull;
    const u64 C22 = pack2(C2, C2);

    load_chunk(0);
    store_chunk(0);
    __syncthreads();

    const int NCH = IDIM / 16;  // 16
    for (int c = 0; c < NCH; c++) {
        const int buf = c & 1;
        if (c + 1 < NCH) load_chunk((c + 1) * 16);

#pragma unroll
        for (int j = 0; j < 16; j += 2) {
            // U/V lanes = (b, b+1) pairs; P/Q lanes = (p_i, p_i) broadcast
            ulonglong2 U0 = *(const ulonglong2*)&su[buf][j][bl];
            ulonglong2 V0 = *(const ulonglong2*)&sv[buf][j][bl];
            ulonglong2 P0 = *(const ulonglong2*)&sp[buf][j][2 * il];
            ulonglong2 Q0 = *(const ulonglong2*)&sq[buf][j][2 * il];
            ulonglong2 U1 = *(const ulonglong2*)&su[buf][j + 1][bl];
            ulonglong2 V1 = *(const ulonglong2*)&sv[buf][j + 1][bl];
            ulonglong2 P1 = *(const ulonglong2*)&sp[buf][j + 1][2 * il];
            ulonglong2 Q1 = *(const ulonglong2*)&sq[buf][j + 1][2 * il];

#define PHOT_STEP(ACC, UBP0, VBP0, UBP1, VBP1, PII0, QII0, PII1, QII1)  \
            {                                                           \
                u64 da = fma2(VBP0, QII0, C22);                         \
                da = fma2(UBP0, PII0, da);                              \
                u64 db = fma2(VBP1, QII1, C22);                         \
                db = fma2(UBP1, PII1, db);                              \
                u64 s = add2(da, db);                                   \
                u64 m = mul2(da, db);                                   \
                ACC = fma2(s, rcp2(m), ACC);                            \
            }

            PHOT_STEP(acc00, U0.x, V0.x, U1.x, V1.x, P0.x, Q0.x, P1.x, Q1.x);
            PHOT_STEP(acc01, U0.x, V0.x, U1.x, V1.x, P0.y, Q0.y, P1.y, Q1.y);
            PHOT_STEP(acc10, U0.y, V0.y, U1.y, V1.y, P0.x, Q0.x, P1.x, Q1.x);
            PHOT_STEP(acc11, U0.y, V0.y, U1.y, V1.y, P0.y, Q0.y, P1.y, Q1.y);
#undef PHOT_STEP
        }

        if (c + 1 < NCH) store_chunk((c + 1) & 1);
        __syncthreads();
    }

    // Epilogue: acc lanes (lo,hi) = b-pair rows; out[b, i0+il .. +1]
    float a00l, a00h, a01l, a01h, a10l, a10h, a11l, a11h;
    unpack2(acc00, a00l, a00h);
    unpack2(acc01, a01l, a01h);
    unpack2(acc10, a10l, a10h);
    unpack2(acc11, a11l, a11h);

    const float base = (float)IDIM;
    float* op = out + (size_t)(b0 + bl) * ODIM + i0 + il;
    float2 r;
    r.x = fmaf(D, a00l, base); r.y = fmaf(D, a01l, base);
    *(float2*)(op + 0 * ODIM) = r;
    r.x = fmaf(D, a00h, base); r.y = fmaf(D, a01h, base);
    *(float2*)(op + 1 * ODIM) = r;
    r.x = fmaf(D, a10l, base); r.y = fmaf(D, a11l, base);
    *(float2*)(op + 2 * ODIM) = r;
    r.x = fmaf(D, a10h, base); r.y = fmaf(D, a11h, base);
    *(float2*)(op + 3 * ODIM) = r;
}

extern "C" void kernel_launch(void* const* d_in, const int* in_sizes, int n_in,
                              void* d_out, int out_size) {
    const float* x   = (const float*)d_in[0];  // input_matrix [2048, 256]
    const float* off = (const float*)d_in[1];  // phase_offset [256, 256]
    float* out = (float*)d_out;                // [2048, 256]

    const double PI = 3.14159265358979323846;
    const double RADIUS = 5e-6, KAPPA = 0.1, N_EFF = 3.48, LAMBDA = 1.55e-6,
                 LOSS_A = 0.99;
    double t = sqrt(1.0 - KAPPA);
    double at = LOSS_A * t;
    float K  = (float)(2.0 * at);
    float C2 = (float)(1.0 + at * at);
    float D  = (float)(-(1.0 - t * t) * (1.0 - LOSS_A * LOSS_A));
    float phi0 = (float)fmod(2.0 * PI * N_EFF * (2.0 * PI * RADIUS) / LAMBDA,
                             2.0 * PI);

    prep_uv<<<dim3(IDIM / 32, BDIM / 32), 256>>>(x, K, phi0);
    prep_pq<<<dim3(IDIM / 32, ODIM / 32), 256>>>(off);

    dim3 grid(ODIM / 32, BDIM / 64);  // (8, 32) = 256 blocks
    photonic_main<<<grid, 256>>>(out, C2, D);
}

// round 4
// speedup vs baseline: 1.3713x; 1.0452x over previous
#include <cuda_runtime.h>
#include <math.h>

// Problem dims
#define BDIM 2048
#define ODIM 256
#define IDIM 256

typedef unsigned long long u64;

// Scratch (no cudaMalloc allowed).
// g_u[j][b] = -K*cos(phi0 + x[b,j])   (sign folded for fma)
// g_v[j][b] =  K*sin(phi0 + x[b,j])
// g_pd[j][2i..2i+1] = {cos(off[i,j]), cos(off[i,j])}   (dup for f32x2 bcast)
// g_qd[j][2i..2i+1] = {sin(off[i,j]), sin(off[i,j])}
__device__ float g_u[IDIM * BDIM];
__device__ float g_v[IDIM * BDIM];
__device__ float g_pd[IDIM * 2 * ODIM];
__device__ float g_qd[IDIM * 2 * ODIM];

// ---------- packed f32x2 helpers (sm_100+) ----------
__device__ __forceinline__ u64 fma2(u64 a, u64 b, u64 c) {
    u64 d;
    asm("fma.rn.f32x2 %0, %1, %2, %3;" : "=l"(d) : "l"(a), "l"(b), "l"(c));
    return d;
}
__device__ __forceinline__ u64 add2(u64 a, u64 b) {
    u64 d;
    asm("add.rn.f32x2 %0, %1, %2;" : "=l"(d) : "l"(a), "l"(b));
    return d;
}
__device__ __forceinline__ u64 mul2(u64 a, u64 b) {
    u64 d;
    asm("mul.rn.f32x2 %0, %1, %2;" : "=l"(d) : "l"(a), "l"(b));
    return d;
}
__device__ __forceinline__ float frcp(float x) {
    float r;
    asm("rcp.approx.ftz.f32 %0, %1;" : "=f"(r) : "f"(x));
    return r;
}
__device__ __forceinline__ u64 rcp2(u64 x) {
    float lo, hi;
    asm("mov.b64 {%0, %1}, %2;" : "=f"(lo), "=f"(hi) : "l"(x));
    lo = frcp(lo);
    hi = frcp(hi);
    u64 r;
    asm("mov.b64 %0, {%1, %2};" : "=l"(r) : "f"(lo), "f"(hi));
    return r;
}
__device__ __forceinline__ u64 pack2(float lo, float hi) {
    u64 r;
    asm("mov.b64 %0, {%1, %2};" : "=l"(r) : "f"(lo), "f"(hi));
    return r;
}
__device__ __forceinline__ void unpack2(u64 v, float& lo, float& hi) {
    asm("mov.b64 {%0, %1}, %2;" : "=f"(lo), "=f"(hi) : "l"(v));
}

// ---------- fused prep: one launch for uv (512 blocks) + pq (64 blocks) ----
__global__ void prep_all(const float* __restrict__ x,
                         const float* __restrict__ off, float K, float phi0) {
    __shared__ float tc[32][33];
    __shared__ float ts[32][33];
    const int bx = blockIdx.x;
    if (bx < 512) {
        // uv: 64 b-tiles x 8 j-tiles of 32x32
        const int b0 = (bx >> 3) * 32;
        const int j0 = (bx & 7) * 32;
#pragma unroll
        for (int k = 0; k < 4; k++) {
            int lin = threadIdx.x + k * 256;
            int bl = lin >> 5, jl = lin & 31;
            float s, c;
            __sincosf(phi0 + x[(b0 + bl) * IDIM + j0 + jl], &s, &c);
            tc[jl][bl] = c;
            ts[jl][bl] = s;
        }
        __syncthreads();
#pragma unroll
        for (int k = 0; k < 4; k++) {
            int lin = threadIdx.x + k * 256;
            int jl = lin >> 5, bl = lin & 31;
            g_u[(j0 + jl) * BDIM + b0 + bl] = -K * tc[jl][bl];
            g_v[(j0 + jl) * BDIM + b0 + bl] = K * ts[jl][bl];
        }
    } else {
        // pq: 8 i-tiles x 8 j-tiles of 32x32, duplicated pairs
        const int r = bx - 512;
        const int i0 = (r >> 3) * 32;
        const int j0 = (r & 7) * 32;
#pragma unroll
        for (int k = 0; k < 4; k++) {
            int lin = threadIdx.x + k * 256;
            int il = lin >> 5, jl = lin & 31;
            float s, c;
            __sincosf(off[(i0 + il) * IDIM + j0 + jl], &s, &c);
            tc[jl][il] = c;
            ts[jl][il] = s;
        }
        __syncthreads();
#pragma unroll
        for (int k = 0; k < 4; k++) {
            int lin = threadIdx.x + k * 256;
            int jl = lin >> 5, il = lin & 31;
            float c = tc[jl][il], s = ts[jl][il];
            float2 cc = {c, c}, ss = {s, s};
            *(float2*)&g_pd[(j0 + jl) * (2 * ODIM) + 2 * (i0 + il)] = cc;
            *(float2*)&g_qd[(j0 + jl) * (2 * ODIM) + 2 * (i0 + il)] = ss;
        }
    }
}

// ---------- main: BM=64, BN=32, BK=16, 256 thr, 4b x 2i per thread --------
// out[b,i] = IDIM + D * sum_j 1/(C2 + g_u[j,b]*p[i,j] + g_v[j,b]*q[i,j])
// Packed over b-pairs (f32x2); quad-j combining: one rcp per 4 j:
//   1/d0+1/d1+1/d2+1/d3 = (s01*m23 + s23*m01) / (m01*m23)
__global__ __launch_bounds__(256, 2) void photonic_main(float* __restrict__ out,
                                                        float C2, float D) {
    __shared__ float su[2][16][64];
    __shared__ float sv[2][16][64];
    __shared__ float sp[2][16][64];
    __shared__ float sq[2][16][64];

    const int tid = threadIdx.x;
    const int i0 = blockIdx.x * 32;
    const int b0 = blockIdx.y * 64;

    const int bl = (tid & 15) * 4;   // 4 consecutive b (2 packed slots)
    const int il = (tid >> 4) * 2;   // 2 consecutive i

    const int lrow = tid >> 4;        // 0..15
    const int lcol = (tid & 15) * 4;  // 0..60

    float4 ru, rv, rp, rq;
    auto load_chunk = [&](int jc) {
        ru = *(const float4*)(g_u + (size_t)(jc + lrow) * BDIM + b0 + lcol);
        rv = *(const float4*)(g_v + (size_t)(jc + lrow) * BDIM + b0 + lcol);
        rp = *(const float4*)(g_pd + (size_t)(jc + lrow) * (2 * ODIM) + 2 * i0 + lcol);
        rq = *(const float4*)(g_qd + (size_t)(jc + lrow) * (2 * ODIM) + 2 * i0 + lcol);
    };
    auto store_chunk = [&](int buf) {
        *(float4*)&su[buf][lrow][lcol] = ru;
        *(float4*)&sv[buf][lrow][lcol] = rv;
        *(float4*)&sp[buf][lrow][lcol] = rp;
        *(float4*)&sq[buf][lrow][lcol] = rq;
    };

    // acc[a], a = slot*2 + i_sub; lanes (lo,hi) = b-pair of that slot
    u64 acc[4];
#pragma unroll
    for (int a = 0; a < 4; a++) acc[a] = 0ull;
    const u64 C22 = pack2(C2, C2);

    load_chunk(0);
    store_chunk(0);
    __syncthreads();

    const int NCH = IDIM / 16;  // 16
    for (int c = 0; c < NCH; c++) {
        const int buf = c & 1;
        if (c + 1 < NCH) load_chunk((c + 1) * 16);

#pragma unroll
        for (int j = 0; j < 16; j += 4) {
            u64 d[4][4];  // [k][a]
#pragma unroll
            for (int k = 0; k < 4; k++) {
                ulonglong2 U = *(const ulonglong2*)&su[buf][j + k][bl];
                ulonglong2 V = *(const ulonglong2*)&sv[buf][j + k][bl];
                ulonglong2 P = *(const ulonglong2*)&sp[buf][j + k][2 * il];
                ulonglong2 Q = *(const ulonglong2*)&sq[buf][j + k][2 * il];
                d[k][0] = fma2(U.x, P.x, fma2(V.x, Q.x, C22));
                d[k][1] = fma2(U.x, P.y, fma2(V.x, Q.y, C22));
                d[k][2] = fma2(U.y, P.x, fma2(V.y, Q.x, C22));
                d[k][3] = fma2(U.y, P.y, fma2(V.y, Q.y, C22));
            }
#pragma unroll
            for (int a = 0; a < 4; a++) {
                u64 s01 = add2(d[0][a], d[1][a]);
                u64 m01 = mul2(d[0][a], d[1][a]);
                u64 s23 = add2(d[2][a], d[3][a]);
                u64 m23 = mul2(d[2][a], d[3][a]);
                u64 num = mul2(s01, m23);
                num = fma2(s23, m01, num);
                u64 den = mul2(m01, m23);
                acc[a] = fma2(num, rcp2(den), acc[a]);
            }
        }

        if (c + 1 < NCH) store_chunk((c + 1) & 1);
        __syncthreads();
    }

    // Epilogue: acc[a=slot*2+ii] lanes (lo,hi) = rows (bl+2*slot, bl+2*slot+1)
    const float base = (float)IDIM;
#pragma unroll
    for (int s = 0; s < 2; s++) {
        float a0l, a0h, a1l, a1h;
        unpack2(acc[s * 2 + 0], a0l, a0h);
        unpack2(acc[s * 2 + 1], a1l, a1h);
        float* op = out + (size_t)(b0 + bl + 2 * s) * ODIM + i0 + il;
        float2 r;
        r.x = fmaf(D, a0l, base);
        r.y = fmaf(D, a1l, base);
        *(float2*)op = r;
        r.x = fmaf(D, a0h, base);
        r.y = fmaf(D, a1h, base);
        *(float2*)(op + ODIM) = r;
    }
}

extern "C" void kernel_launch(void* const* d_in, const int* in_sizes, int n_in,
                              void* d_out, int out_size) {
    const float* x   = (const float*)d_in[0];  // input_matrix [2048, 256]
    const float* off = (const float*)d_in[1];  // phase_offset [256, 256]
    float* out = (float*)d_out;                // [2048, 256]

    const double PI = 3.14159265358979323846;
    const double RADIUS = 5e-6, KAPPA = 0.1, N_EFF = 3.48, LAMBDA = 1.55e-6,
                 LOSS_A = 0.99;
    double t = sqrt(1.0 - KAPPA);
    double at = LOSS_A * t;
    float K  = (float)(2.0 * at);
    float C2 = (float)(1.0 + at * at);
    float D  = (float)(-(1.0 - t * t) * (1.0 - LOSS_A * LOSS_A));
    float phi0 = (float)fmod(2.0 * PI * N_EFF * (2.0 * PI * RADIUS) / LAMBDA,
                             2.0 * PI);

    prep_all<<<576, 256>>>(x, off, K, phi0);

    dim3 grid(ODIM / 32, BDIM / 64);  // (8, 32) = 256 blocks
    photonic_main<<<grid, 256>>>(out, C2, D);
}